// round 16
// baseline (speedup 1.0000x reference)
#include <cuda_runtime.h>
#include <stdint.h>

#define NN 100000
#define EE 1600000
#define FF 128
#define DD 64
#define GG 512
#define TMM 128   // rows per CTA tile
#define AGG_CH 2048

// ---------------- device scratch ----------------
__device__ __align__(16) float g_y[NN * DD];
__device__ __align__(16) float g_z[NN * DD];
__device__ __align__(16) float g_h[NN * DD];
__device__ __align__(16) int g_deg[NN];
__device__ __align__(16) int g_cur[NN + 4];
__device__ __align__(16) int g_rowptr[NN + 4];
__device__ int g_cnt[GG];
__device__ int g_ctr;
__device__ __align__(8) int2 g_epack[EE];
__device__ double g_sq[DD];
__device__ __align__(16) float g_bnp0[2 * DD];
__device__ __align__(16) float g_bnp1[2 * DD];
__device__ __align__(16) float g_pool[2 * GG * DD];

__device__ __forceinline__ void red1(float* p, float x) {
    asm volatile("red.global.add.f32 [%0], %1;" :: "l"(p), "f"(x) : "memory");
}
__device__ __forceinline__ uint32_t smem_u32(const void* p) {
    return (uint32_t)__cvta_generic_to_shared(p);
}
__device__ __forceinline__ void ldm_x4(uint32_t* a, uint32_t addr) {
    asm volatile("ldmatrix.sync.aligned.m8n8.x4.shared.b16 {%0,%1,%2,%3}, [%4];"
                 : "=r"(a[0]), "=r"(a[1]), "=r"(a[2]), "=r"(a[3]) : "r"(addr));
}
__device__ __forceinline__ void ldm_x2t(uint32_t* b, uint32_t addr) {
    asm volatile("ldmatrix.sync.aligned.m8n8.x2.trans.shared.b16 {%0,%1}, [%2];"
                 : "=r"(b[0]), "=r"(b[1]) : "r"(addr));
}
__device__ __forceinline__ void mma16816(float* c, const uint32_t* a, const uint32_t* b) {
    asm volatile("mma.sync.aligned.m16n8k16.row.col.f32.bf16.bf16.f32 "
                 "{%0,%1,%2,%3}, {%4,%5,%6,%7}, {%8,%9}, {%0,%1,%2,%3};"
                 : "+f"(c[0]), "+f"(c[1]), "+f"(c[2]), "+f"(c[3])
                 : "r"(a[0]), "r"(a[1]), "r"(a[2]), "r"(a[3]), "r"(b[0]), "r"(b[1]));
}
__device__ __forceinline__ uint32_t bfpack(float a, float b) {
    return (__float_as_uint(a) >> 16) | (__float_as_uint(b) & 0xFFFF0000u);
}
__device__ __forceinline__ float bfhi(float a) {
    return __uint_as_float(__float_as_uint(a) & 0xFFFF0000u);
}

// ---------------- single-block exclusive scan (int4), zeroes g_deg after use ----------------
__global__ void scan_kernel() {
    __shared__ int part[512];
    const int CH4 = 49;
    int tid = threadIdx.x;
    int b4 = tid * CH4;
    int4* D4 = reinterpret_cast<int4*>(g_deg);
    const int NV4 = NN / 4;
    int s = 0;
    for (int i = 0; i < CH4; i++) {
        int idx = b4 + i;
        if (idx < NV4) {
            int4 d = D4[idx];
            s += d.x + d.y + d.z + d.w;
        }
    }
    part[tid] = s;
    __syncthreads();
    for (int off = 1; off < 512; off <<= 1) {
        int v = (tid >= off) ? part[tid - off] : 0;
        __syncthreads();
        part[tid] += v;
        __syncthreads();
    }
    int run = (tid == 0) ? 0 : part[tid - 1];
    int4* R4 = reinterpret_cast<int4*>(g_rowptr);
    int4* C4 = reinterpret_cast<int4*>(g_cur);
    for (int i = 0; i < CH4; i++) {
        int idx = b4 + i;
        if (idx < NV4) {
            int4 d = D4[idx];
            int4 r;
            r.x = run;
            r.y = r.x + d.x;
            r.z = r.y + d.y;
            r.w = r.z + d.z;
            run = r.w + d.w;
            R4[idx] = r;
            C4[idx] = r;
            D4[idx] = make_int4(0, 0, 0, 0);
        }
    }
    if (tid == 511) g_rowptr[NN] = run;
}

// ---------------- CSR fill: 4 edges/thread for atomic MLP ----------------
__global__ void fill_kernel(const int* __restrict__ ei, const float* __restrict__ ew) {
    int t0 = (blockIdx.x * 256 + threadIdx.x) * 4;
    int src[4], dst[4], pos[4];
    float w[4];
#pragma unroll
    for (int j = 0; j < 4; j++) {
        int e = t0 + j;
        if (e < EE) {
            src[j] = ei[e];
            dst[j] = ei[EE + e];
            w[j] = ew[e];
        }
    }
#pragma unroll
    for (int j = 0; j < 4; j++) {
        int e = t0 + j;
        if (e < EE) pos[j] = atomicAdd(&g_cur[dst[j]], 1);
    }
#pragma unroll
    for (int j = 0; j < 4; j++) {
        int e = t0 + j;
        if (e < EE) g_epack[pos[j]] = make_int2(src[j], __float_as_int(w[j]));
    }
}

// ============ tensor-core GEMM: C[128 x 64] tile of A[N x K] @ W[K x 64] ============
// split-bf16 3-pass. Software-pipelined staging.
// MODE 0: A = A_in, write g_y. If hist_ei != null, blocks >= nb_gemm do the histogram.
// MODE 1: A = g_h with BN0 scale/shift on load, write g_y
// MODE 2: A = g_z, epilogue relu+bias, g_h store, stats+pool, LAST BLOCK computes BN params
// MODE 3: like 2, no g_h store
template <int K, int MODE>
__global__ __launch_bounds__(256) void gemm_kernel(
    const float* __restrict__ A_in, const float* __restrict__ W,
    const float* __restrict__ bias, const int* __restrict__ batch, int layer,
    const int* __restrict__ hist_ei, int nb_gemm,
    const float* __restrict__ gamma, const float* __restrict__ beta) {
    const int LDA = 20, APL = TMM * LDA;
    const int LDW = 36, WPL = 32 * LDW;
    __shared__ __align__(16) char s_buf[35840];
    __shared__ float s_sq[64];
    __shared__ int s_g[TMM];
    __shared__ int s_last;
    uint32_t* As = reinterpret_cast<uint32_t*>(s_buf);
    uint32_t* Ws = reinterpret_cast<uint32_t*>(s_buf + 2 * TMM * LDA * 4);
    float* Ht = reinterpret_cast<float*>(s_buf);

    if (MODE == 0 && hist_ei != 0 && (int)blockIdx.x >= nb_gemm) {
        int t = (blockIdx.x - nb_gemm) * 256 + threadIdx.x;
        if (t < EE) atomicAdd(&g_deg[hist_ei[EE + t]], 1);
        if (t < NN) atomicAdd(&g_cnt[batch[t]], 1);
        return;
    }

    const float* A = (MODE == 1) ? g_h : ((MODE >= 2) ? g_z : A_in);
    const int KF4 = K / 4;
    int base = blockIdx.x * TMM;
    int tid = threadIdx.x;
    int wid = tid >> 5;
    int lane = tid & 31;
    if (MODE >= 2) {
        if (tid < 64) s_sq[tid] = 0.f;
        for (int i = tid; i < TMM; i += 256) {
            int gn = base + i;
            s_g[i] = batch[gn < NN ? gn : NN - 1];
        }
    }

    float4 ra[4];
    float4 rw[2];
    auto loadA = [&](int kc) {
#pragma unroll
        for (int it = 0; it < 4; it++) {
            int i = tid + it * 256;
            int n = i >> 3, k4 = i & 7;
            int gn = base + n;
            float4 v = make_float4(0.f, 0.f, 0.f, 0.f);
            if (gn < NN) v = reinterpret_cast<const float4*>(A)[(size_t)gn * KF4 + (kc >> 2) + k4];
            if (MODE == 1) {
                int ci = (kc >> 2) + k4;
                float4 sc = reinterpret_cast<const float4*>(g_bnp0)[ci];
                float4 sh = reinterpret_cast<const float4*>(g_bnp0)[16 + ci];
                v.x = v.x * sc.x + sh.x;
                v.y = v.y * sc.y + sh.y;
                v.z = v.z * sc.z + sh.z;
                v.w = v.w * sc.w + sh.w;
            }
            ra[it] = v;
        }
    };
    auto loadW = [&](int kc) {
#pragma unroll
        for (int it = 0; it < 2; it++) {
            int i = tid + it * 256;
            int k = i >> 4, j4 = i & 15;
            rw[it] = reinterpret_cast<const float4*>(W)[(size_t)(kc + k) * 16 + j4];
        }
    };
    auto storeAW = [&]() {
#pragma unroll
        for (int it = 0; it < 4; it++) {
            int i = tid + it * 256;
            int n = i >> 3, k4 = i & 7;
            float4 v = ra[it];
            int off = n * LDA + k4 * 2;
            As[off] = bfpack(v.x, v.y);
            As[off + 1] = bfpack(v.z, v.w);
            As[APL + off] = bfpack(v.x - bfhi(v.x), v.y - bfhi(v.y));
            As[APL + off + 1] = bfpack(v.z - bfhi(v.z), v.w - bfhi(v.w));
        }
#pragma unroll
        for (int it = 0; it < 2; it++) {
            int i = tid + it * 256;
            int k = i >> 4, j4 = i & 15;
            float4 v = rw[it];
            int off = k * LDW + j4 * 2;
            Ws[off] = bfpack(v.x, v.y);
            Ws[off + 1] = bfpack(v.z, v.w);
            Ws[WPL + off] = bfpack(v.x - bfhi(v.x), v.y - bfhi(v.y));
            Ws[WPL + off + 1] = bfpack(v.z - bfhi(v.z), v.w - bfhi(v.w));
        }
    };

    float acc[8][4];
#pragma unroll
    for (int nt = 0; nt < 8; nt++) {
        acc[nt][0] = 0.f; acc[nt][1] = 0.f; acc[nt][2] = 0.f; acc[nt][3] = 0.f;
    }

    loadA(0);
    loadW(0);
    for (int kc = 0; kc < K; kc += 32) {
        storeAW();
        __syncthreads();
        if (kc + 32 < K) {
            loadA(kc + 32);
            loadW(kc + 32);
        }
#pragma unroll
        for (int s = 0; s < 2; s++) {
            uint32_t ah[4], al[4];
            uint32_t aaddr = smem_u32(&As[(wid * 16 + (lane & 15)) * LDA + s * 8 + ((lane >> 4) << 2)]);
            ldm_x4(ah, aaddr);
            ldm_x4(al, aaddr + APL * 4);
#pragma unroll
            for (int nt = 0; nt < 8; nt++) {
                uint32_t bh[2], bl[2];
                uint32_t baddr = smem_u32(&Ws[(s * 16 + (lane & 15)) * LDW + nt * 4]);
                ldm_x2t(bh, baddr);
                ldm_x2t(bl, baddr + WPL * 4);
                mma16816(acc[nt], ah, bh);
                mma16816(acc[nt], ah, bl);
                mma16816(acc[nt], al, bh);
            }
        }
        __syncthreads();
    }

    int rl0 = wid * 16 + (lane >> 2);
    int r0 = base + rl0;
    int cb = (lane & 3) * 2;
    if (MODE <= 1) {
#pragma unroll
        for (int nt = 0; nt < 8; nt++) {
            int col = nt * 8 + cb;
            if (r0 < NN)
                *reinterpret_cast<float2*>(&g_y[r0 * 64 + col]) = make_float2(acc[nt][0], acc[nt][1]);
            if (r0 + 8 < NN)
                *reinterpret_cast<float2*>(&g_y[(r0 + 8) * 64 + col]) = make_float2(acc[nt][2], acc[nt][3]);
        }
    } else {
#pragma unroll
        for (int nt = 0; nt < 8; nt++) {
            int col = nt * 8 + cb;
            float2 bb = *reinterpret_cast<const float2*>(&bias[col]);
#pragma unroll
            for (int h2 = 0; h2 < 2; h2++) {
                int rl = rl0 + h2 * 8;
                int r = base + rl;
                float v0 = 0.f, v1 = 0.f;
                if (r < NN) {
                    v0 = fmaxf(acc[nt][h2 * 2 + 0] + bb.x, 0.f);
                    v1 = fmaxf(acc[nt][h2 * 2 + 1] + bb.y, 0.f);
                    if (MODE == 2)
                        *reinterpret_cast<float2*>(&g_h[r * 64 + col]) = make_float2(v0, v1);
                }
                *reinterpret_cast<float2*>(&Ht[rl * 68 + col]) = make_float2(v0, v1);
            }
        }
        __syncthreads();
        int col = tid & 63;
        int rs = (tid >> 6) * 32;
        float* poolL = &g_pool[layer * GG * DD];
        float ps = 0.f, pq = 0.f;
        int cg = s_g[rs];
#pragma unroll 4
        for (int r = rs; r < rs + 32; r++) {
            float v = Ht[r * 68 + col];
            int gr = s_g[r];
            if (gr != cg) {
                red1(&poolL[cg * 64 + col], ps);
                ps = 0.f;
                cg = gr;
            }
            ps += v;
            pq += v * v;
        }
        red1(&poolL[cg * 64 + col], ps);
        atomicAdd(&s_sq[col], pq);
        __syncthreads();
        if (tid < 64) atomicAdd(&g_sq[tid], (double)s_sq[tid]);

        // ---- last-block BN finalize (threadFenceReduction pattern) ----
        __threadfence();
        __syncthreads();
        if (tid == 0) {
            int old = atomicAdd(&g_ctr, 1);
            s_last = (old == (int)gridDim.x - 1) ? 1 : 0;
        }
        __syncthreads();
        if (s_last) {
            if (tid < DD) {
                int f = tid;
                const float* pp = &g_pool[layer * GG * DD];
                float s0 = 0.f, s1 = 0.f, s2 = 0.f, s3 = 0.f;
                for (int g = 0; g < GG; g += 4) {
                    s0 += pp[(g + 0) * DD + f];
                    s1 += pp[(g + 1) * DD + f];
                    s2 += pp[(g + 2) * DD + f];
                    s3 += pp[(g + 3) * DD + f];
                }
                float s = (s0 + s1) + (s2 + s3);
                double q = g_sq[f];
                g_sq[f] = 0.0;
                float mu = s / (float)NN;
                float var = (float)(q / (double)NN) - mu * mu;
                float rstd = rsqrtf(var + 1e-5f);
                float sc = gamma[f] * rstd;
                float* bp = layer ? g_bnp1 : g_bnp0;
                bp[f] = sc;
                bp[DD + f] = beta[f] - mu * sc;
            }
            if (tid == 0) g_ctr = 0;   // reset for next fused gemm / graph replay
        }
    }
}

// ---------------- CSR aggregation: 32 nodes/block, 8 threads/node, 2 float4/thread ----------------
__global__ __launch_bounds__(256) void agg_kernel(const float* __restrict__ b1) {
    __shared__ int2 s_e[AGG_CH];
    __shared__ int s_ptr[33];
    int nb0 = blockIdx.x * 32;
    int tid = threadIdx.x;
    if (tid <= 32) {
        int n = nb0 + tid;
        s_ptr[tid] = g_rowptr[n > NN ? NN : n];
    }
    __syncthreads();
    int e0 = s_ptr[0];
    int e1 = s_ptr[32];
    int g8 = tid >> 3;
    int c = tid & 7;
    int node = nb0 + g8;
    bool valid = node < NN;
    int my_s = valid ? s_ptr[g8] : 0;
    int my_e = valid ? s_ptr[g8 + 1] : 0;
    const float4* Y4 = reinterpret_cast<const float4*>(g_y);
    float4 a0 = make_float4(0.f, 0.f, 0.f, 0.f);
    float4 a1 = a0;
    if (valid) {
        a0 = Y4[node * 16 + c];
        a1 = Y4[node * 16 + c + 8];
    }
    for (int cs = e0; cs < e1; cs += AGG_CH) {
        int ce = min(cs + AGG_CH, e1);
        __syncthreads();
        for (int i = tid; i < ce - cs; i += 256) s_e[i] = g_epack[cs + i];
        __syncthreads();
        int lo = max(my_s, cs);
        int hi = min(my_e, ce);
        int i = lo;
        for (; i + 2 <= hi; i += 2) {
            int2 ea = s_e[i - cs];
            int2 eb = s_e[i + 1 - cs];
            int ba = ea.x * 16 + c;
            int bb = eb.x * 16 + c;
            float4 va0 = Y4[ba];
            float4 va1 = Y4[ba + 8];
            float4 vb0 = Y4[bb];
            float4 vb1 = Y4[bb + 8];
            float wa = __int_as_float(ea.y);
            float wb = __int_as_float(eb.y);
            a0.x += wa * va0.x + wb * vb0.x;
            a0.y += wa * va0.y + wb * vb0.y;
            a0.z += wa * va0.z + wb * vb0.z;
            a0.w += wa * va0.w + wb * vb0.w;
            a1.x += wa * va1.x + wb * vb1.x;
            a1.y += wa * va1.y + wb * vb1.y;
            a1.z += wa * va1.z + wb * vb1.z;
            a1.w += wa * va1.w + wb * vb1.w;
        }
        if (i < hi) {
            int2 ea = s_e[i - cs];
            int ba = ea.x * 16 + c;
            float4 va0 = Y4[ba];
            float4 va1 = Y4[ba + 8];
            float wa = __int_as_float(ea.y);
            a0.x += wa * va0.x;
            a0.y += wa * va0.y;
            a0.z += wa * va0.z;
            a0.w += wa * va0.w;
            a1.x += wa * va1.x;
            a1.y += wa * va1.y;
            a1.z += wa * va1.z;
            a1.w += wa * va1.w;
        }
    }
    if (valid) {
        float4 b0 = reinterpret_cast<const float4*>(b1)[c];
        float4 b14 = reinterpret_cast<const float4*>(b1)[c + 8];
        reinterpret_cast<float4*>(g_z)[node * 16 + c] =
            make_float4(fmaxf(a0.x + b0.x, 0.f), fmaxf(a0.y + b0.y, 0.f),
                        fmaxf(a0.z + b0.z, 0.f), fmaxf(a0.w + b0.w, 0.f));
        reinterpret_cast<float4*>(g_z)[node * 16 + c + 8] =
            make_float4(fmaxf(a1.x + b14.x, 0.f), fmaxf(a1.y + b14.y, 0.f),
                        fmaxf(a1.z + b14.z, 0.f), fmaxf(a1.w + b14.w, 0.f));
    }
}

// ---------------- classifier head; self-cleans g_pool and g_cnt ----------------
__global__ void head_kernel(const float* __restrict__ wf, const float* __restrict__ bf,
                            const float* __restrict__ wf1, const float* __restrict__ bf1,
                            const float* __restrict__ wf2, const float* __restrict__ bf2,
                            float* __restrict__ out) {
    __shared__ float gs[128];
    __shared__ float as_[64];
    __shared__ float bs[64];
    int g = blockIdx.x;
    int j = threadIdx.x;
    float cnt = (float)g_cnt[g];
    gs[j]      = g_pool[g * 64 + j] * g_bnp0[j] + cnt * g_bnp0[64 + j];
    gs[64 + j] = g_pool[(GG + g) * 64 + j] * g_bnp1[j] + cnt * g_bnp1[64 + j];
    g_pool[g * 64 + j] = 0.f;
    g_pool[(GG + g) * 64 + j] = 0.f;
    if (j == 0) g_cnt[g] = 0;
    __syncthreads();
    float acc = bf[j];
#pragma unroll 8
    for (int k = 0; k < 128; k++) acc += gs[k] * wf[k * 64 + j];
    as_[j] = fmaxf(acc, 0.f);
    __syncthreads();
    acc = bf1[j];
#pragma unroll 8
    for (int k = 0; k < 64; k++) acc += as_[k] * wf1[k * 64 + j];
    bs[j] = fmaxf(acc, 0.f);
    __syncthreads();
    if (j == 0) {
        float l0 = bf2[0], l1 = bf2[1];
        for (int k = 0; k < 64; k++) {
            l0 += bs[k] * wf2[k * 2 + 0];
            l1 += bs[k] * wf2[k * 2 + 1];
        }
        float m = fmaxf(l0, l1);
        float lse = m + logf(expf(l0 - m) + expf(l1 - m));
        out[g * 2 + 0] = l0 - lse;
        out[g * 2 + 1] = l1 - lse;
    }
}

extern "C" void kernel_launch(void* const* d_in, const int* in_sizes, int n_in,
                              void* d_out, int out_size) {
    (void)in_sizes; (void)n_in; (void)out_size;
    const float* x     = (const float*)d_in[0];
    const int*   ei    = (const int*)d_in[1];
    const float* ew    = (const float*)d_in[2];
    const int*   batch = (const int*)d_in[3];
    const float* w1a = (const float*)d_in[4];
    const float* b1a = (const float*)d_in[5];
    const float* w2a = (const float*)d_in[6];
    const float* b2a = (const float*)d_in[7];
    const float* gamma0 = (const float*)d_in[8];
    const float* beta0  = (const float*)d_in[9];
    const float* w1b = (const float*)d_in[10];
    const float* b1b = (const float*)d_in[11];
    const float* w2b = (const float*)d_in[12];
    const float* b2b = (const float*)d_in[13];
    const float* gamma1 = (const float*)d_in[14];
    const float* beta1  = (const float*)d_in[15];
    const float* wf  = (const float*)d_in[16];
    const float* bf  = (const float*)d_in[17];
    const float* wf1 = (const float*)d_in[18];
    const float* bf1 = (const float*)d_in[19];
    const float* wf2 = (const float*)d_in[20];
    const float* bf2 = (const float*)d_in[21];
    float* out = (float*)d_out;

    int nb = (NN + TMM - 1) / TMM;         // 782
    int eb = (EE + 255) / 256;             // 6250
    int eb4 = (EE + 1023) / 1024;          // 1563
    int ab = (NN + 31) / 32;               // 3125

    // ---- layer 0 projection + fused degree/count histogram ----
    gemm_kernel<128, 0><<<nb + eb, 256>>>(x, w1a, (const float*)0, batch, 0, ei, nb,
                                          (const float*)0, (const float*)0);
    scan_kernel<<<1, 512>>>();
    fill_kernel<<<eb4, 256>>>(ei, ew);
    agg_kernel<<<ab, 256>>>(b1a);
    gemm_kernel<64, 2><<<nb, 256>>>((const float*)0, w2a, b2a, batch, 0, (const int*)0, nb,
                                    gamma0, beta0);        // BN finalize fused (last block)

    // ---- layer 1 ----
    gemm_kernel<64, 1><<<nb, 256>>>((const float*)0, w1b, (const float*)0, batch, 0,
                                    (const int*)0, nb, (const float*)0, (const float*)0);
    agg_kernel<<<ab, 256>>>(b1b);
    gemm_kernel<64, 3><<<nb, 256>>>((const float*)0, w2b, b2b, batch, 1, (const int*)0, nb,
                                    gamma1, beta1);        // BN finalize fused (last block)

    // ---- head ----
    head_kernel<<<GG, 64>>>(wf, bf, wf1, bf1, wf2, bf2, out);
}

// round 17
// speedup vs baseline: 1.0183x; 1.0183x over previous
#include <cuda_runtime.h>
#include <stdint.h>

#define NN 100000
#define EE 1600000
#define FF 128
#define DD 64
#define GG 512
#define TMM 128   // rows per CTA tile
#define AGG_CH 2048

// ---------------- device scratch ----------------
__device__ __align__(16) float g_y[NN * DD];
__device__ __align__(16) uint32_t g_y16[NN * DD / 2];   // fp16x2 shadow of g_y (gathers)
__device__ __align__(16) float g_z[NN * DD];
__device__ __align__(16) float g_h[NN * DD];
__device__ __align__(16) int g_deg[NN];
__device__ __align__(16) int g_cur[NN + 4];
__device__ __align__(16) int g_rowptr[NN + 4];
__device__ int g_cnt[GG];
__device__ __align__(8) int2 g_epack[EE];
__device__ double g_sq[DD];
__device__ __align__(16) float g_bnp0[2 * DD];
__device__ __align__(16) float g_bnp1[2 * DD];
__device__ __align__(16) float g_pool[2 * GG * DD];

__device__ __forceinline__ void red1(float* p, float x) {
    asm volatile("red.global.add.f32 [%0], %1;" :: "l"(p), "f"(x) : "memory");
}
__device__ __forceinline__ uint32_t smem_u32(const void* p) {
    return (uint32_t)__cvta_generic_to_shared(p);
}
__device__ __forceinline__ void ldm_x4(uint32_t* a, uint32_t addr) {
    asm volatile("ldmatrix.sync.aligned.m8n8.x4.shared.b16 {%0,%1,%2,%3}, [%4];"
                 : "=r"(a[0]), "=r"(a[1]), "=r"(a[2]), "=r"(a[3]) : "r"(addr));
}
__device__ __forceinline__ void ldm_x2t(uint32_t* b, uint32_t addr) {
    asm volatile("ldmatrix.sync.aligned.m8n8.x2.trans.shared.b16 {%0,%1}, [%2];"
                 : "=r"(b[0]), "=r"(b[1]) : "r"(addr));
}
__device__ __forceinline__ void mma16816(float* c, const uint32_t* a, const uint32_t* b) {
    asm volatile("mma.sync.aligned.m16n8k16.row.col.f32.bf16.bf16.f32 "
                 "{%0,%1,%2,%3}, {%4,%5,%6,%7}, {%8,%9}, {%0,%1,%2,%3};"
                 : "+f"(c[0]), "+f"(c[1]), "+f"(c[2]), "+f"(c[3])
                 : "r"(a[0]), "r"(a[1]), "r"(a[2]), "r"(a[3]), "r"(b[0]), "r"(b[1]));
}
__device__ __forceinline__ uint32_t bfpack(float a, float b) {
    return (__float_as_uint(a) >> 16) | (__float_as_uint(b) & 0xFFFF0000u);
}
__device__ __forceinline__ float bfhi(float a) {
    return __uint_as_float(__float_as_uint(a) & 0xFFFF0000u);
}
// fp16x2 pack/unpack via PTX (no cuda_fp16.h dependency)
__device__ __forceinline__ uint32_t f2h2(float a, float b) {
    uint32_t r;
    asm("{.reg .f16 lo, hi;\n cvt.rn.f16.f32 lo, %1;\n cvt.rn.f16.f32 hi, %2;\n"
        " mov.b32 %0, {lo, hi};}" : "=r"(r) : "f"(a), "f"(b));
    return r;
}
__device__ __forceinline__ float2 h2f2(uint32_t h) {
    float2 r;
    asm("{.reg .f16 lo, hi;\n mov.b32 {lo, hi}, %2;\n cvt.f32.f16 %0, lo;\n"
        " cvt.f32.f16 %1, hi;}" : "=f"(r.x), "=f"(r.y) : "r"(h));
    return r;
}

// ---------------- single-block exclusive scan (int4), zeroes g_deg after use ----------------
__global__ void scan_kernel() {
    __shared__ int part[512];
    const int CH4 = 49;
    int tid = threadIdx.x;
    int b4 = tid * CH4;
    int4* D4 = reinterpret_cast<int4*>(g_deg);
    const int NV4 = NN / 4;
    int s = 0;
    for (int i = 0; i < CH4; i++) {
        int idx = b4 + i;
        if (idx < NV4) {
            int4 d = D4[idx];
            s += d.x + d.y + d.z + d.w;
        }
    }
    part[tid] = s;
    __syncthreads();
    for (int off = 1; off < 512; off <<= 1) {
        int v = (tid >= off) ? part[tid - off] : 0;
        __syncthreads();
        part[tid] += v;
        __syncthreads();
    }
    int run = (tid == 0) ? 0 : part[tid - 1];
    int4* R4 = reinterpret_cast<int4*>(g_rowptr);
    int4* C4 = reinterpret_cast<int4*>(g_cur);
    for (int i = 0; i < CH4; i++) {
        int idx = b4 + i;
        if (idx < NV4) {
            int4 d = D4[idx];
            int4 r;
            r.x = run;
            r.y = r.x + d.x;
            r.z = r.y + d.y;
            r.w = r.z + d.z;
            run = r.w + d.w;
            R4[idx] = r;
            C4[idx] = r;
            D4[idx] = make_int4(0, 0, 0, 0);
        }
    }
    if (tid == 511) g_rowptr[NN] = run;
}

// ---------------- CSR fill: 4 edges/thread for atomic MLP ----------------
__global__ void fill_kernel(const int* __restrict__ ei, const float* __restrict__ ew) {
    int t0 = (blockIdx.x * 256 + threadIdx.x) * 4;
    int src[4], dst[4], pos[4];
    float w[4];
#pragma unroll
    for (int j = 0; j < 4; j++) {
        int e = t0 + j;
        if (e < EE) {
            src[j] = ei[e];
            dst[j] = ei[EE + e];
            w[j] = ew[e];
        }
    }
#pragma unroll
    for (int j = 0; j < 4; j++) {
        int e = t0 + j;
        if (e < EE) pos[j] = atomicAdd(&g_cur[dst[j]], 1);
    }
#pragma unroll
    for (int j = 0; j < 4; j++) {
        int e = t0 + j;
        if (e < EE) g_epack[pos[j]] = make_int2(src[j], __float_as_int(w[j]));
    }
}

// ============ tensor-core GEMM: C[128 x 64] tile of A[N x K] @ W[K x 64] ============
// split-bf16 3-pass. Software-pipelined staging.
// MODE 0: A = A_in, write g_y + g_y16. If hist_ei != null, blocks >= nb_gemm do histogram.
// MODE 1: A = g_h with BN0 scale/shift on load, write g_y + g_y16
// MODE 2: A = g_z, epilogue relu+bias, store g_h, stats + pooling
// MODE 3: like 2, no g_h store
template <int K, int MODE>
__global__ __launch_bounds__(256) void gemm_kernel(
    const float* __restrict__ A_in, const float* __restrict__ W,
    const float* __restrict__ bias, const int* __restrict__ batch, int layer,
    const int* __restrict__ hist_ei, int nb_gemm) {
    const int LDA = 20, APL = TMM * LDA;
    const int LDW = 36, WPL = 32 * LDW;
    __shared__ __align__(16) char s_buf[35840];
    __shared__ float s_sq[64];
    __shared__ int s_g[TMM];
    uint32_t* As = reinterpret_cast<uint32_t*>(s_buf);
    uint32_t* Ws = reinterpret_cast<uint32_t*>(s_buf + 2 * TMM * LDA * 4);
    float* Ht = reinterpret_cast<float*>(s_buf);

    if (MODE == 0 && hist_ei != 0 && (int)blockIdx.x >= nb_gemm) {
        int t = (blockIdx.x - nb_gemm) * 256 + threadIdx.x;
        if (t < EE) atomicAdd(&g_deg[hist_ei[EE + t]], 1);
        if (t < NN) atomicAdd(&g_cnt[batch[t]], 1);
        return;
    }

    const float* A = (MODE == 1) ? g_h : ((MODE >= 2) ? g_z : A_in);
    const int KF4 = K / 4;
    int base = blockIdx.x * TMM;
    int tid = threadIdx.x;
    int wid = tid >> 5;
    int lane = tid & 31;
    if (MODE >= 2) {
        if (tid < 64) s_sq[tid] = 0.f;
        for (int i = tid; i < TMM; i += 256) {
            int gn = base + i;
            s_g[i] = batch[gn < NN ? gn : NN - 1];
        }
    }

    float4 ra[4];
    float4 rw[2];
    auto loadA = [&](int kc) {
#pragma unroll
        for (int it = 0; it < 4; it++) {
            int i = tid + it * 256;
            int n = i >> 3, k4 = i & 7;
            int gn = base + n;
            float4 v = make_float4(0.f, 0.f, 0.f, 0.f);
            if (gn < NN) v = reinterpret_cast<const float4*>(A)[(size_t)gn * KF4 + (kc >> 2) + k4];
            if (MODE == 1) {
                int ci = (kc >> 2) + k4;
                float4 sc = reinterpret_cast<const float4*>(g_bnp0)[ci];
                float4 sh = reinterpret_cast<const float4*>(g_bnp0)[16 + ci];
                v.x = v.x * sc.x + sh.x;
                v.y = v.y * sc.y + sh.y;
                v.z = v.z * sc.z + sh.z;
                v.w = v.w * sc.w + sh.w;
            }
            ra[it] = v;
        }
    };
    auto loadW = [&](int kc) {
#pragma unroll
        for (int it = 0; it < 2; it++) {
            int i = tid + it * 256;
            int k = i >> 4, j4 = i & 15;
            rw[it] = reinterpret_cast<const float4*>(W)[(size_t)(kc + k) * 16 + j4];
        }
    };
    auto storeAW = [&]() {
#pragma unroll
        for (int it = 0; it < 4; it++) {
            int i = tid + it * 256;
            int n = i >> 3, k4 = i & 7;
            float4 v = ra[it];
            int off = n * LDA + k4 * 2;
            As[off] = bfpack(v.x, v.y);
            As[off + 1] = bfpack(v.z, v.w);
            As[APL + off] = bfpack(v.x - bfhi(v.x), v.y - bfhi(v.y));
            As[APL + off + 1] = bfpack(v.z - bfhi(v.z), v.w - bfhi(v.w));
        }
#pragma unroll
        for (int it = 0; it < 2; it++) {
            int i = tid + it * 256;
            int k = i >> 4, j4 = i & 15;
            float4 v = rw[it];
            int off = k * LDW + j4 * 2;
            Ws[off] = bfpack(v.x, v.y);
            Ws[off + 1] = bfpack(v.z, v.w);
            Ws[WPL + off] = bfpack(v.x - bfhi(v.x), v.y - bfhi(v.y));
            Ws[WPL + off + 1] = bfpack(v.z - bfhi(v.z), v.w - bfhi(v.w));
        }
    };

    float acc[8][4];
#pragma unroll
    for (int nt = 0; nt < 8; nt++) {
        acc[nt][0] = 0.f; acc[nt][1] = 0.f; acc[nt][2] = 0.f; acc[nt][3] = 0.f;
    }

    loadA(0);
    loadW(0);
    for (int kc = 0; kc < K; kc += 32) {
        storeAW();
        __syncthreads();
        if (kc + 32 < K) {
            loadA(kc + 32);
            loadW(kc + 32);
        }
#pragma unroll
        for (int s = 0; s < 2; s++) {
            uint32_t ah[4], al[4];
            uint32_t aaddr = smem_u32(&As[(wid * 16 + (lane & 15)) * LDA + s * 8 + ((lane >> 4) << 2)]);
            ldm_x4(ah, aaddr);
            ldm_x4(al, aaddr + APL * 4);
#pragma unroll
            for (int nt = 0; nt < 8; nt++) {
                uint32_t bh[2], bl[2];
                uint32_t baddr = smem_u32(&Ws[(s * 16 + (lane & 15)) * LDW + nt * 4]);
                ldm_x2t(bh, baddr);
                ldm_x2t(bl, baddr + WPL * 4);
                mma16816(acc[nt], ah, bh);
                mma16816(acc[nt], ah, bl);
                mma16816(acc[nt], al, bh);
            }
        }
        __syncthreads();
    }

    int rl0 = wid * 16 + (lane >> 2);
    int r0 = base + rl0;
    int cb = (lane & 3) * 2;
    if (MODE <= 1) {
#pragma unroll
        for (int nt = 0; nt < 8; nt++) {
            int col = nt * 8 + cb;
            int u = nt * 4 + (lane & 3);          // u32 index within row of g_y16
            if (r0 < NN) {
                *reinterpret_cast<float2*>(&g_y[r0 * 64 + col]) = make_float2(acc[nt][0], acc[nt][1]);
                g_y16[r0 * 32 + u] = f2h2(acc[nt][0], acc[nt][1]);
            }
            if (r0 + 8 < NN) {
                *reinterpret_cast<float2*>(&g_y[(r0 + 8) * 64 + col]) = make_float2(acc[nt][2], acc[nt][3]);
                g_y16[(r0 + 8) * 32 + u] = f2h2(acc[nt][2], acc[nt][3]);
            }
        }
    } else {
#pragma unroll
        for (int nt = 0; nt < 8; nt++) {
            int col = nt * 8 + cb;
            float2 bb = *reinterpret_cast<const float2*>(&bias[col]);
#pragma unroll
            for (int h2 = 0; h2 < 2; h2++) {
                int rl = rl0 + h2 * 8;
                int r = base + rl;
                float v0 = 0.f, v1 = 0.f;
                if (r < NN) {
                    v0 = fmaxf(acc[nt][h2 * 2 + 0] + bb.x, 0.f);
                    v1 = fmaxf(acc[nt][h2 * 2 + 1] + bb.y, 0.f);
                    if (MODE == 2)
                        *reinterpret_cast<float2*>(&g_h[r * 64 + col]) = make_float2(v0, v1);
                }
                *reinterpret_cast<float2*>(&Ht[rl * 68 + col]) = make_float2(v0, v1);
            }
        }
        __syncthreads();
        int col = tid & 63;
        int rs = (tid >> 6) * 32;
        float* poolL = &g_pool[layer * GG * DD];
        float ps = 0.f, pq = 0.f;
        int cg = s_g[rs];
#pragma unroll 4
        for (int r = rs; r < rs + 32; r++) {
            float v = Ht[r * 68 + col];
            int gr = s_g[r];
            if (gr != cg) {
                red1(&poolL[cg * 64 + col], ps);
                ps = 0.f;
                cg = gr;
            }
            ps += v;
            pq += v * v;
        }
        red1(&poolL[cg * 64 + col], ps);
        atomicAdd(&s_sq[col], pq);
        __syncthreads();
        if (tid < 64) atomicAdd(&g_sq[tid], (double)s_sq[tid]);
    }
}

// ---- CSR aggregation: 32 nodes/block, 8 threads/node; fp16 gathers, fp32 self/accum ----
__global__ __launch_bounds__(256) void agg_kernel(const float* __restrict__ b1) {
    __shared__ int2 s_e[AGG_CH];
    __shared__ int s_ptr[33];
    int nb0 = blockIdx.x * 32;
    int tid = threadIdx.x;
    if (tid <= 32) {
        int n = nb0 + tid;
        s_ptr[tid] = g_rowptr[n > NN ? NN : n];
    }
    __syncthreads();
    int e0 = s_ptr[0];
    int e1 = s_ptr[32];
    int g8 = tid >> 3;
    int c = tid & 7;              // cols 8c..8c+7
    int node = nb0 + g8;
    bool valid = node < NN;
    int my_s = valid ? s_ptr[g8] : 0;
    int my_e = valid ? s_ptr[g8 + 1] : 0;
    const float4* Y4 = reinterpret_cast<const float4*>(g_y);
    const uint4* Y16 = reinterpret_cast<const uint4*>(g_y16);
    float a[8] = {0.f, 0.f, 0.f, 0.f, 0.f, 0.f, 0.f, 0.f};
    if (valid) {
        float4 s0 = Y4[node * 16 + c * 2];
        float4 s1 = Y4[node * 16 + c * 2 + 1];
        a[0] = s0.x; a[1] = s0.y; a[2] = s0.z; a[3] = s0.w;
        a[4] = s1.x; a[5] = s1.y; a[6] = s1.z; a[7] = s1.w;
    }
    for (int cs = e0; cs < e1; cs += AGG_CH) {
        int ce = min(cs + AGG_CH, e1);
        __syncthreads();
        for (int i = tid; i < ce - cs; i += 256) s_e[i] = g_epack[cs + i];
        __syncthreads();
        int lo = max(my_s, cs);
        int hi = min(my_e, ce);
        int i = lo;
        for (; i + 2 <= hi; i += 2) {
            int2 ea = s_e[i - cs];
            int2 eb = s_e[i + 1 - cs];
            uint4 va = Y16[ea.x * 8 + c];
            uint4 vb = Y16[eb.x * 8 + c];
            float wa = __int_as_float(ea.y);
            float wb = __int_as_float(eb.y);
            float2 p;
            p = h2f2(va.x); a[0] += wa * p.x; a[1] += wa * p.y;
            p = h2f2(va.y); a[2] += wa * p.x; a[3] += wa * p.y;
            p = h2f2(va.z); a[4] += wa * p.x; a[5] += wa * p.y;
            p = h2f2(va.w); a[6] += wa * p.x; a[7] += wa * p.y;
            p = h2f2(vb.x); a[0] += wb * p.x; a[1] += wb * p.y;
            p = h2f2(vb.y); a[2] += wb * p.x; a[3] += wb * p.y;
            p = h2f2(vb.z); a[4] += wb * p.x; a[5] += wb * p.y;
            p = h2f2(vb.w); a[6] += wb * p.x; a[7] += wb * p.y;
        }
        if (i < hi) {
            int2 ea = s_e[i - cs];
            uint4 va = Y16[ea.x * 8 + c];
            float wa = __int_as_float(ea.y);
            float2 p;
            p = h2f2(va.x); a[0] += wa * p.x; a[1] += wa * p.y;
            p = h2f2(va.y); a[2] += wa * p.x; a[3] += wa * p.y;
            p = h2f2(va.z); a[4] += wa * p.x; a[5] += wa * p.y;
            p = h2f2(va.w); a[6] += wa * p.x; a[7] += wa * p.y;
        }
    }
    if (valid) {
        float4 b0 = reinterpret_cast<const float4*>(b1)[c * 2];
        float4 b14 = reinterpret_cast<const float4*>(b1)[c * 2 + 1];
        reinterpret_cast<float4*>(g_z)[node * 16 + c * 2] =
            make_float4(fmaxf(a[0] + b0.x, 0.f), fmaxf(a[1] + b0.y, 0.f),
                        fmaxf(a[2] + b0.z, 0.f), fmaxf(a[3] + b0.w, 0.f));
        reinterpret_cast<float4*>(g_z)[node * 16 + c * 2 + 1] =
            make_float4(fmaxf(a[4] + b14.x, 0.f), fmaxf(a[5] + b14.y, 0.f),
                        fmaxf(a[6] + b14.z, 0.f), fmaxf(a[7] + b14.w, 0.f));
    }
}

// ---------------- BN finalize: mean from pool, var from g_sq; resets g_sq ----------------
__global__ void bn_fin_kernel(const float* __restrict__ gamma, const float* __restrict__ beta,
                              int layer) {
    int f = threadIdx.x;
    if (f >= DD) return;
    const float* pp = &g_pool[layer * GG * DD];
    float s0 = 0.f, s1 = 0.f, s2 = 0.f, s3 = 0.f;
    for (int g = 0; g < GG; g += 4) {
        s0 += pp[(g + 0) * DD + f];
        s1 += pp[(g + 1) * DD + f];
        s2 += pp[(g + 2) * DD + f];
        s3 += pp[(g + 3) * DD + f];
    }
    float s = (s0 + s1) + (s2 + s3);
    double q = g_sq[f];
    g_sq[f] = 0.0;
    float mu = s / (float)NN;
    float var = (float)(q / (double)NN) - mu * mu;
    float rstd = rsqrtf(var + 1e-5f);
    float sc = gamma[f] * rstd;
    float* bp = layer ? g_bnp1 : g_bnp0;
    bp[f] = sc;
    bp[DD + f] = beta[f] - mu * sc;
}

// ---------------- classifier head; self-cleans g_pool and g_cnt ----------------
__global__ void head_kernel(const float* __restrict__ wf, const float* __restrict__ bf,
                            const float* __restrict__ wf1, const float* __restrict__ bf1,
                            const float* __restrict__ wf2, const float* __restrict__ bf2,
                            float* __restrict__ out) {
    __shared__ float gs[128];
    __shared__ float as_[64];
    __shared__ float bs[64];
    int g = blockIdx.x;
    int j = threadIdx.x;
    float cnt = (float)g_cnt[g];
    gs[j]      = g_pool[g * 64 + j] * g_bnp0[j] + cnt * g_bnp0[64 + j];
    gs[64 + j] = g_pool[(GG + g) * 64 + j] * g_bnp1[j] + cnt * g_bnp1[64 + j];
    g_pool[g * 64 + j] = 0.f;
    g_pool[(GG + g) * 64 + j] = 0.f;
    if (j == 0) g_cnt[g] = 0;
    __syncthreads();
    float acc = bf[j];
#pragma unroll 8
    for (int k = 0; k < 128; k++) acc += gs[k] * wf[k * 64 + j];
    as_[j] = fmaxf(acc, 0.f);
    __syncthreads();
    acc = bf1[j];
#pragma unroll 8
    for (int k = 0; k < 64; k++) acc += as_[k] * wf1[k * 64 + j];
    bs[j] = fmaxf(acc, 0.f);
    __syncthreads();
    if (j == 0) {
        float l0 = bf2[0], l1 = bf2[1];
        for (int k = 0; k < 64; k++) {
            l0 += bs[k] * wf2[k * 2 + 0];
            l1 += bs[k] * wf2[k * 2 + 1];
        }
        float m = fmaxf(l0, l1);
        float lse = m + logf(expf(l0 - m) + expf(l1 - m));
        out[g * 2 + 0] = l0 - lse;
        out[g * 2 + 1] = l1 - lse;
    }
}

extern "C" void kernel_launch(void* const* d_in, const int* in_sizes, int n_in,
                              void* d_out, int out_size) {
    (void)in_sizes; (void)n_in; (void)out_size;
    const float* x     = (const float*)d_in[0];
    const int*   ei    = (const int*)d_in[1];
    const float* ew    = (const float*)d_in[2];
    const int*   batch = (const int*)d_in[3];
    const float* w1a = (const float*)d_in[4];
    const float* b1a = (const float*)d_in[5];
    const float* w2a = (const float*)d_in[6];
    const float* b2a = (const float*)d_in[7];
    const float* gamma0 = (const float*)d_in[8];
    const float* beta0  = (const float*)d_in[9];
    const float* w1b = (const float*)d_in[10];
    const float* b1b = (const float*)d_in[11];
    const float* w2b = (const float*)d_in[12];
    const float* b2b = (const float*)d_in[13];
    const float* gamma1 = (const float*)d_in[14];
    const float* beta1  = (const float*)d_in[15];
    const float* wf  = (const float*)d_in[16];
    const float* bf  = (const float*)d_in[17];
    const float* wf1 = (const float*)d_in[18];
    const float* bf1 = (const float*)d_in[19];
    const float* wf2 = (const float*)d_in[20];
    const float* bf2 = (const float*)d_in[21];
    float* out = (float*)d_out;

    int nb = (NN + TMM - 1) / TMM;         // 782
    int eb = (EE + 255) / 256;             // 6250
    int eb4 = (EE + 1023) / 1024;          // 1563
    int ab = (NN + 31) / 32;               // 3125

    // ---- layer 0 projection + fused degree/count histogram ----
    gemm_kernel<128, 0><<<nb + eb, 256>>>(x, w1a, (const float*)0, batch, 0, ei, nb);
    scan_kernel<<<1, 512>>>();
    fill_kernel<<<eb4, 256>>>(ei, ew);
    agg_kernel<<<ab, 256>>>(b1a);
    gemm_kernel<64, 2><<<nb, 256>>>((const float*)0, w2a, b2a, batch, 0, (const int*)0, nb);
    bn_fin_kernel<<<1, 64>>>(gamma0, beta0, 0);

    // ---- layer 1 ----
    gemm_kernel<64, 1><<<nb, 256>>>((const float*)0, w1b, (const float*)0, batch, 0,
                                    (const int*)0, nb);
    agg_kernel<<<ab, 256>>>(b1b);
    gemm_kernel<64, 3><<<nb, 256>>>((const float*)0, w2b, b2b, batch, 1, (const int*)0, nb);
    bn_fin_kernel<<<1, 64>>>(gamma1, beta1, 1);

    // ---- head ----
    head_kernel<<<GG, 64>>>(wf, bf, wf1, bf1, wf2, bf2, out);
}